// round 17
// baseline (speedup 1.0000x reference)
#include <cuda_runtime.h>
#include <cstdint>

#define T_STEPS 256
#define NBLK    (T_STEPS / 2)            // 128 two-step blocks
#define BATCH   8
#define NPROBES 4
#define CLUSTER 8
#define NWARPS  16                       // warp owns ONE local row
#define NTHREADS (NWARPS * 32)           // 512
#define NCTAS   (BATCH * CLUSTER)        // 64
#define FULLM   0xffffffffu

typedef unsigned long long ull;

// ---------- f32x2 packed helpers (sm_103a) ----------
__device__ __forceinline__ ull pack2(float lo, float hi) {
    ull r; asm("mov.b64 %0, {%1, %2};" : "=l"(r) : "f"(lo), "f"(hi)); return r;
}
__device__ __forceinline__ void unpack2(ull a, float& lo, float& hi) {
    asm("mov.b64 {%0, %1}, %2;" : "=f"(lo), "=f"(hi) : "l"(a));
}
__device__ __forceinline__ ull add2(ull a, ull b) {
    ull r; asm("add.rn.f32x2 %0, %1, %2;" : "=l"(r) : "l"(a), "l"(b)); return r;
}
__device__ __forceinline__ ull fma2(ull a, ull b, ull c) {
    ull r; asm("fma.rn.f32x2 %0, %1, %2, %3;" : "=l"(r) : "l"(a), "l"(b), "l"(c)); return r;
}

// ---------- cluster / mbarrier helpers ----------
__device__ __forceinline__ uint32_t smem_u32(const void* p) {
    uint32_t a;
    asm("{ .reg .u64 t; cvta.to.shared.u64 t, %1; cvt.u32.u64 %0, t; }" : "=r"(a) : "l"(p));
    return a;
}
__device__ __forceinline__ uint32_t mapa_u32(uint32_t addr, uint32_t rank) {
    uint32_t r; asm("mapa.shared::cluster.u32 %0, %1, %2;" : "=r"(r) : "r"(addr), "r"(rank));
    return r;
}
__device__ __forceinline__ void st_cluster_v2(uint32_t addr, ull a, ull b) {
    asm volatile("st.shared::cluster.v2.u64 [%0], {%1, %2};" :: "r"(addr), "l"(a), "l"(b) : "memory");
}
__device__ __forceinline__ void mbar_init(uint32_t addr, uint32_t cnt) {
    asm volatile("mbarrier.init.shared.b64 [%0], %1;" :: "r"(addr), "r"(cnt) : "memory");
}
__device__ __forceinline__ void mbar_arrive_local(uint32_t addr) {
    asm volatile("mbarrier.arrive.release.cta.shared::cta.b64 _, [%0];" :: "r"(addr) : "memory");
}
__device__ __forceinline__ void mbar_arrive_remote(uint32_t addr) {
    asm volatile("mbarrier.arrive.release.cluster.shared::cluster.b64 _, [%0];" :: "r"(addr) : "memory");
}
__device__ __forceinline__ void mbar_wait_cta(uint32_t addr, uint32_t ph) {
    uint32_t done;
    do {
        asm volatile("{\n\t.reg .pred p;\n\t"
                     "mbarrier.try_wait.parity.acquire.cta.shared::cta.b64 p, [%1], %2, 0x989680;\n\t"
                     "selp.b32 %0, 1, 0, p;\n\t}"
                     : "=r"(done) : "r"(addr), "r"(ph) : "memory");
    } while (!done);
}
__device__ __forceinline__ void mbar_wait_cluster(uint32_t addr, uint32_t ph) {
    uint32_t done;
    do {
        asm volatile("{\n\t.reg .pred p;\n\t"
                     "mbarrier.try_wait.parity.acquire.cluster.shared::cta.b64 p, [%1], %2, 0x989680;\n\t"
                     "selp.b32 %0, 1, 0, p;\n\t}"
                     : "=r"(done) : "r"(addr), "r"(ph) : "memory");
    } while (!done);
}
__device__ __forceinline__ void cluster_sync() {
    asm volatile("barrier.cluster.arrive.aligned;" ::: "memory");
    asm volatile("barrier.cluster.wait.aligned;"   ::: "memory");
}

__device__ float    g_psum[NPROBES] = {0.f, 0.f, 0.f, 0.f};
__device__ unsigned g_ticket        = 0u;

// dynamic smem (bytes):
//   [0, 40960)       halo : ull[2][20][2][64]  extended row index j=0..19; local row = j-2
//                      slot 0 = row(t+2), slot 1 = row(t+1); ghost slots 0,1,18,19 peer-pushed
//   [40960, 41984)   xsh  : float[256]
//   [41984, 42240)   wmbar: ull[16][2]
#define OFF_XSH   40960
#define OFF_WMBAR 41984
#define SMEM_BYTES 42256
#define HBUF 2560          // ull per halo buffer (20*2*64)
#define HBUF_BYTES 20480

__global__ __launch_bounds__(NTHREADS, 1) __cluster_dims__(CLUSTER, 1, 1)
void wave_fused_kernel(const float* __restrict__ x,
                       const float* __restrict__ c,
                       const int* __restrict__ probes_i32,
                       float* __restrict__ out)
{
    extern __shared__ char smem_raw[];
    ull*   halo = reinterpret_cast<ull*>(smem_raw);
    float* xsh  = reinterpret_cast<float*>(smem_raw + OFF_XSH);

    const uint32_t smem_base  = smem_u32(smem_raw);
    const uint32_t wmbar_base = smem_base + OFF_WMBAR;   // wmbar[w][s] at +(w*2+s)*8

    uint32_t rank; asm("mov.u32 %0, %%cluster_ctarank;" : "=r"(rank));
    const int b   = blockIdx.x / CLUSTER;
    const int tid = threadIdx.x;
    const int w   = tid >> 5;                 // warp 0..15 : local row w
    const int l   = tid & 31;
    const int c0  = l << 2;
    const int r   = (int)rank * NWARPS + w;   // my global row

    const float dtb   = 0.5f * 0.005f;
    const float cy2s  = -1.0f - dtb;                   // -1.0025
    const float denom = 4.0f + (0.5f * 0.005f) / 0.5f; // 4.005
    const float invd  = 1.0f / denom;

    const ull NEG4  = pack2(-4.0f, -4.0f);
    const ull CY2P  = pack2(cy2s * invd, cy2s * invd);
    const ull TWO2P = pack2(2.0f * invd, 2.0f * invd);

    for (int t = tid; t < T_STEPS; t += NTHREADS)
        xsh[t] = x[t * BATCH + b];
    for (int i = tid; i < 2 * HBUF; i += NTHREADS)
        halo[i] = 0ull;

    // kk' = 0.25*c^2*invd for rows r-1, r, r+1 (clamped; out-of-grid values unused)
    ull kkmx, kkmy, kkax, kkay, kkpx, kkpy;
    {
        int rm = (r > 0)   ? r - 1 : 0;
        int rp = (r < 127) ? r + 1 : 127;
        float4 cm = *reinterpret_cast<const float4*>(&c[rm * 128 + c0]);
        float4 ca = *reinterpret_cast<const float4*>(&c[r  * 128 + c0]);
        float4 cp = *reinterpret_cast<const float4*>(&c[rp * 128 + c0]);
        kkmx = pack2(0.25f * cm.x * cm.x * invd, 0.25f * cm.y * cm.y * invd);
        kkmy = pack2(0.25f * cm.z * cm.z * invd, 0.25f * cm.w * cm.w * invd);
        kkax = pack2(0.25f * ca.x * ca.x * invd, 0.25f * ca.y * ca.y * invd);
        kkay = pack2(0.25f * ca.z * ca.z * invd, 0.25f * ca.w * ca.w * invd);
        kkpx = pack2(0.25f * cp.x * cp.x * invd, 0.25f * cp.y * cp.y * invd);
        kkpy = pack2(0.25f * cp.z * cp.z * invd, 0.25f * cp.w * cp.w * invd);
    }

    ull y1lo = 0, y1hi = 0, y2lo = 0, y2hi = 0;   // my row at t, t-1

    // ---- probe decoding (runtime dtype detection: int32 vs int64) ----
    int pxv[NPROBES], pyv[NPROBES];
    {
        int odd_or = probes_i32[1] | probes_i32[3] | probes_i32[5] | probes_i32[7];
        if (odd_or == 0) {
#pragma unroll
            for (int p = 0; p < NPROBES; p++) { pxv[p] = probes_i32[4 * p]; pyv[p] = probes_i32[4 * p + 2]; }
        } else {
#pragma unroll
            for (int p = 0; p < NPROBES; p++) { pxv[p] = probes_i32[2 * p]; pyv[p] = probes_i32[2 * p + 1]; }
        }
    }
    float pacc[NPROBES];
    int   pidx[NPROBES];          // component 0..3, or -1
    bool  pown = false;
#pragma unroll
    for (int p = 0; p < NPROBES; p++) {
        pacc[p] = 0.f;
        bool mine = (pxv[p] == r) && (pyv[p] >= c0) && (pyv[p] < c0 + 4);
        pidx[p] = mine ? (pyv[p] - c0) : -1;
        pown = pown || mine;
    }

    // source (64,64): lane 16, lo of lo pair
    const bool src_own = (r == 64) && (l == 16);
    const bool src_gm  = (r == 65) && (l == 16);   // my ghost r-1 is the source row
    const bool src_gp  = (r == 63) && (l == 16);   // my ghost r+1 is the source row

    const bool has_m1 = (r >= 1);     // ghost row r-1 exists
    const bool has_p1 = (r <= 126);   // ghost row r+1 exists

    // remote producers feed me iff I'm within 2 of a seam with a peer
    const bool remote_prod = ((w <= 1) && (rank > 0)) || ((w >= 14) && (rank < CLUSTER - 1));

    // remote data push: my row fills the peer's ghost slots
    const bool push_up = (w <= 1)  && (rank > 0);              // -> up-peer halo idx 18+w
    const bool push_dn = (w >= 14) && (rank < CLUSTER - 1);    // -> dn-peer halo idx w-14
    uint32_t push_base = 0;
    if (push_up) push_base = mapa_u32(smem_base + ((18 + w) * 128 + 2 * l) * 8, rank - 1);
    if (push_dn) push_base = mapa_u32(smem_base + ((w - 14) * 128 + 2 * l) * 8, rank + 1);

    // arrive targets: owners of rows r-1, r-2, r+1, r+2 (local or remote)
    auto loc_mbar = [&](int tw) { return wmbar_base + (tw * 2) * 8; };
    uint32_t ca1 = 0, ca2 = 0, ca3 = 0, ca4 = 0;
    const bool am1 = (r >= 1), am2 = (r >= 2), ap1 = (r <= 126), ap2 = (r <= 125);
    const bool m1r = (w == 0), m2r = (w <= 1), p1r = (w == 15), p2r = (w >= 14);
    {
        uint32_t upk = (rank > 0) ? rank - 1 : rank;
        uint32_t dnk = (rank < CLUSTER - 1) ? rank + 1 : rank;
        ca1 = m1r ? mapa_u32(loc_mbar(15), upk) : loc_mbar(w - 1);
        ca2 = (w >= 2) ? loc_mbar(w - 2)
            : ((w == 1) ? mapa_u32(loc_mbar(15), upk) : mapa_u32(loc_mbar(14), upk));
        ca3 = p1r ? mapa_u32(loc_mbar(0), dnk) : loc_mbar(w + 1);
        ca4 = (w <= 13) ? loc_mbar(w + 2)
            : ((w == 14) ? mapa_u32(loc_mbar(0), dnk) : mapa_u32(loc_mbar(1), dnk));
    }

    const uint32_t my_mbar = loc_mbar(w);
    if (l == 0) {
        uint32_t cnt = (uint32_t)((r >= 1) + (r >= 2) + (r <= 126) + (r <= 125));
        mbar_init(my_mbar, cnt);
        mbar_init(my_mbar + 8, cnt);
    }

    // row update at time t -> t+1
    auto upd = [&](ull ab_lo, ull ab_hi, ull v_lo, ull v_hi,
                   ull bl_lo, ull bl_hi, ull q_lo, ull q_hi,
                   ull kx, ull ky, ull& nv_lo, ull& nv_hi) {
        float vx, vy, vz, vw;
        unpack2(v_lo, vx, vy);
        unpack2(v_hi, vz, vw);
        float lf = __shfl_up_sync(FULLM, vw, 1);
        float rt = __shfl_down_sync(FULLM, vx, 1);
        if (l == 0)  lf = 0.f;
        if (l == 31) rt = 0.f;
        const ull P1 = pack2(lf, vx);
        const ull P2 = pack2(vy, vz);
        const ull P3 = pack2(vw, rt);
        ull lap_lo = fma2(NEG4, v_lo, add2(add2(ab_lo, bl_lo), add2(P1, P2)));
        ull lap_hi = fma2(NEG4, v_hi, add2(add2(ab_hi, bl_hi), add2(P2, P3)));
        nv_lo = fma2(kx, lap_lo, fma2(CY2P, q_lo, TWO2P));
        nv_hi = fma2(ky, lap_hi, fma2(CY2P, q_hi, TWO2P));
    };

    __syncthreads();
    cluster_sync();

    for (int k = 0; k < NBLK; k++) {
        if (k > 0) {
            const uint32_t mb = my_mbar + ((k - 1) & 1) * 8;
            const uint32_t ph = ((k - 1) >> 1) & 1;
            if (remote_prod) mbar_wait_cluster(mb, ph);
            else             mbar_wait_cta(mb, ph);
        }
        const int rd = (k + 1) & 1;

        // ghost loads (uniform extended-halo indexing; unwritten slots stay zero)
        const ull* H = halo + rd * HBUF + 2 * l;
        ulonglong2 hg;
        hg = *reinterpret_cast<const ulonglong2*>(H + (w)     * 128);            ull gm2lo = hg.x, gm2hi = hg.y;
        hg = *reinterpret_cast<const ulonglong2*>(H + (w + 1) * 128);            ull gm1lo = hg.x, gm1hi = hg.y;
        hg = *reinterpret_cast<const ulonglong2*>(H + (w + 1) * 128 + 64);       ull hm1lo = hg.x, hm1hi = hg.y;
        hg = *reinterpret_cast<const ulonglong2*>(H + (w + 3) * 128);            ull gp1lo = hg.x, gp1hi = hg.y;
        hg = *reinterpret_cast<const ulonglong2*>(H + (w + 3) * 128 + 64);       ull hp1lo = hg.x, hp1hi = hg.y;
        hg = *reinterpret_cast<const ulonglong2*>(H + (w + 4) * 128);            ull gp2lo = hg.x, gp2hi = hg.y;

        const float xt1 = xsh[2 * k];
        const float xt2 = xsh[2 * k + 1];

        // ---- step 1 (t -> t+1): ghosts r-1, r+1 and own row r ----
        ull m1lo = 0, m1hi = 0, p1lo = 0, p1hi = 0, n1lo, n1hi;
        if (has_m1)
            upd(gm2lo, gm2hi, gm1lo, gm1hi, y1lo, y1hi, hm1lo, hm1hi, kkmx, kkmy, m1lo, m1hi);
        upd(gm1lo, gm1hi, y1lo, y1hi, gp1lo, gp1hi, y2lo, y2hi, kkax, kkay, n1lo, n1hi);
        if (has_p1)
            upd(y1lo, y1hi, gp1lo, gp1hi, gp2lo, gp2hi, hp1lo, hp1hi, kkpx, kkpy, p1lo, p1hi);

        if (src_own) { float a2, b2; unpack2(n1lo, a2, b2); n1lo = pack2(a2 + xt1, b2); }
        if (src_gm)  { float a2, b2; unpack2(m1lo, a2, b2); m1lo = pack2(a2 + xt1, b2); }
        if (src_gp)  { float a2, b2; unpack2(p1lo, a2, b2); p1lo = pack2(a2 + xt1, b2); }

        // ---- step 2 (t+1 -> t+2): own row only ----
        ull n2lo, n2hi;
        upd(m1lo, m1hi, n1lo, n1hi, p1lo, p1hi, y1lo, y1hi, kkax, kkay, n2lo, n2hi);
        if (src_own) { float a2, b2; unpack2(n2lo, a2, b2); n2lo = pack2(a2 + xt2, b2); }

        y2lo = n1lo; y2hi = n1hi;
        y1lo = n2lo; y1hi = n2hi;

        // ---- publish + arrives (skip after last block) ----
        if (k < NBLK - 1) {
            const int wr = k & 1;
            ull* M = halo + wr * HBUF + (w + 2) * 128 + 2 * l;
            ulonglong2 s0; s0.x = n2lo; s0.y = n2hi;
            ulonglong2 s1; s1.x = n1lo; s1.y = n1hi;
            *reinterpret_cast<ulonglong2*>(M)      = s0;   // slot 0: row(t+2)
            *reinterpret_cast<ulonglong2*>(M + 64) = s1;   // slot 1: row(t+1)

            if (push_up || push_dn) {
                const uint32_t pb = push_base + wr * HBUF_BYTES;
                st_cluster_v2(pb,       n2lo, n2hi);
                st_cluster_v2(pb + 512, n1lo, n1hi);
            }

            __syncwarp();   // lanes' stores visible to lane 0 (release propagates)

            if (l == 0) {
                const uint32_t so = wr * 8;
                if (am1) { if (m1r) mbar_arrive_remote(ca1 + so); else mbar_arrive_local(ca1 + so); }
                if (am2) { if (m2r) mbar_arrive_remote(ca2 + so); else mbar_arrive_local(ca2 + so); }
                if (ap1) { if (p1r) mbar_arrive_remote(ca3 + so); else mbar_arrive_local(ca3 + so); }
                if (ap2) { if (p2r) mbar_arrive_remote(ca4 + so); else mbar_arrive_local(ca4 + so); }
            }
        }

        // ---- probes: own row at t+1 (n1) and t+2 (n2) ----
        if (pown) {
#pragma unroll
            for (int p = 0; p < NPROBES; p++) {
                if (pidx[p] >= 0) {
                    float a1, b1, v1f = 0.f, v2f = 0.f;
                    switch (pidx[p]) {
                        case 0: unpack2(n1lo, a1, b1); v1f = a1; unpack2(n2lo, a1, b1); v2f = a1; break;
                        case 1: unpack2(n1lo, a1, b1); v1f = b1; unpack2(n2lo, a1, b1); v2f = b1; break;
                        case 2: unpack2(n1hi, a1, b1); v1f = a1; unpack2(n2hi, a1, b1); v2f = a1; break;
                        case 3: unpack2(n1hi, a1, b1); v1f = b1; unpack2(n2hi, a1, b1); v2f = b1; break;
                    }
                    pacc[p] += v1f * v1f + v2f * v2f;
                }
            }
        }
    }

#pragma unroll
    for (int p = 0; p < NPROBES; p++)
        if (pidx[p] >= 0) atomicAdd(&g_psum[p], pacc[p]);

    // fused finalization: last of 64 CTAs reduces, writes out, resets globals
    __syncthreads();
    __threadfence();
    if (tid == 0) {
        unsigned ticket = atomicAdd(&g_ticket, 1u);
        if (ticket == NCTAS - 1) {
            float v[NPROBES];
            float s = 0.f;
#pragma unroll
            for (int p = 0; p < NPROBES; p++) { v[p] = atomicAdd(&g_psum[p], 0.0f); s += v[p]; }
#pragma unroll
            for (int p = 0; p < NPROBES; p++) {
                out[p] = v[p] / s;
                atomicExch(&g_psum[p], 0.0f);
            }
            atomicExch(&g_ticket, 0u);
        }
    }
}

extern "C" void kernel_launch(void* const* d_in, const int* in_sizes, int n_in,
                              void* d_out, int out_size)
{
    const float* x      = (const float*)d_in[0];   // (256, 8) f32
    const float* c      = (const float*)d_in[1];   // (128, 128) f32
    const int*   probes = (const int*)d_in[2];     // (4, 2) i32/i64 — detected in-kernel
    float*       out    = (float*)d_out;           // (4,) f32

    cudaFuncSetAttribute(wave_fused_kernel,
                         cudaFuncAttributeMaxDynamicSharedMemorySize, SMEM_BYTES);

    wave_fused_kernel<<<NCTAS, NTHREADS, SMEM_BYTES>>>(x, c, probes, out);
}